// round 3
// baseline (speedup 1.0000x reference)
#include <cuda_runtime.h>
#include <cstdint>

typedef unsigned char u8;
typedef unsigned int u32;

#define BATCH 4096

// ---------------- static device scratch (no allocations allowed) ----------------
// Per-layer LUT-matrices: M[k][a][o] = lut[a + aoff][qw[o*K + k]]
__device__ __align__(128) float g_M1[25 * 256 * 8];     // conv1: K=25, full a-range, O=6 padded to 8
__device__ __align__(128) float g_M2[150 * 128 * 16];   // conv2: K=150, a in [128,255], O=16
__device__ __align__(128) float g_M3[256 * 128 * 120];  // fc1
__device__ __align__(128) float g_M4[120 * 128 * 84];   // fc2
__device__ __align__(128) float g_M5[84 * 128 * 10];    // fc3

__device__ u8    g_qx [BATCH * 784];
__device__ float g_h1 [BATCH * 6 * 144];
__device__ u8    g_qh1[BATCH * 6 * 144];
__device__ float g_h2 [BATCH * 256];
__device__ u8    g_qh2[BATCH * 256];
__device__ float g_h3 [BATCH * 120];
__device__ u8    g_qh3[BATCH * 120];
__device__ float g_h4 [BATCH * 84];
__device__ u8    g_qh4[BATCH * 84];

__device__ u8 g_qw1[150], g_qw2[2400], g_qw3[30720], g_qw4[10080], g_qw5[840];
__device__ float g_sw[5];   // weight scales
__device__ u32 g_amax[5];   // activation max-abs (float bits), per layer input

// ---------------- helpers ----------------
__device__ __forceinline__ float act_scale(int i) {
    float m = __uint_as_float(g_amax[i]);
    return __fdiv_rn(m, 127.0f) + 1e-8f;
}

__device__ __forceinline__ float blockReduceMax(float v, float* sred) {
    #pragma unroll
    for (int off = 16; off; off >>= 1)
        v = fmaxf(v, __shfl_xor_sync(0xFFFFFFFFu, v, off));
    int w = threadIdx.x >> 5;
    int nw = (blockDim.x + 31) >> 5;
    if ((threadIdx.x & 31) == 0) sred[w] = v;
    __syncthreads();
    if (threadIdx.x < 32) {
        v = (threadIdx.x < nw) ? sred[threadIdx.x] : 0.0f;
        #pragma unroll
        for (int off = 16; off; off >>= 1)
            v = fmaxf(v, __shfl_xor_sync(0xFFFFFFFFu, v, off));
    }
    return v;  // valid in thread 0
}

__device__ __forceinline__ u8 quant1(float v, float s) {
    float q = rintf(__fdiv_rn(v, s));
    q = fminf(fmaxf(q, -128.0f), 127.0f);
    return (u8)((int)q + 128);
}

// ---------------- setup kernels ----------------
__global__ void k_zero() {
    if (threadIdx.x < 5) g_amax[threadIdx.x] = 0u;
}

__global__ void k_quant_w(const float* w0, const float* w1, const float* w2,
                          const float* w3, const float* w4) {
    __shared__ float sred[32];
    __shared__ float ss;
    int l = blockIdx.x;
    const float* w; int n; u8* dst;
    if      (l == 0) { w = w0; n = 150;   dst = g_qw1; }
    else if (l == 1) { w = w1; n = 2400;  dst = g_qw2; }
    else if (l == 2) { w = w2; n = 30720; dst = g_qw3; }
    else if (l == 3) { w = w3; n = 10080; dst = g_qw4; }
    else             { w = w4; n = 840;   dst = g_qw5; }
    float m = 0.0f;
    for (int i = threadIdx.x; i < n; i += blockDim.x) m = fmaxf(m, fabsf(w[i]));
    m = blockReduceMax(m, sred);
    if (threadIdx.x == 0) {
        float s = __fdiv_rn(m, 127.0f) + 1e-8f;
        g_sw[l] = s; ss = s;
    }
    __syncthreads();
    float s = ss;
    for (int i = threadIdx.x; i < n; i += blockDim.x) dst[i] = quant1(w[i], s);
}

__global__ void k_buildM(float* dst, const u8* qw, const float* lut,
                         int K, int O, int Opad, int aoff, int nA) {
    int total = K * nA * Opad;
    for (int i = blockIdx.x * blockDim.x + threadIdx.x; i < total;
         i += gridDim.x * blockDim.x) {
        int k = i / (nA * Opad);
        int r = i - k * (nA * Opad);
        int a = r / Opad;
        int o = r - a * Opad;
        dst[i] = (o < O) ? lut[(a + aoff) * 256 + (int)qw[o * K + k]] : 0.0f;
    }
}

__global__ void k_maxabs(const float* src, int n, int idx) {
    __shared__ float sred[32];
    float m = 0.0f;
    for (int i = blockIdx.x * blockDim.x + threadIdx.x; i < n;
         i += gridDim.x * blockDim.x)
        m = fmaxf(m, fabsf(src[i]));
    m = blockReduceMax(m, sred);
    if (threadIdx.x == 0) atomicMax(&g_amax[idx], __float_as_uint(m));
}

__global__ void k_quant_act(const float* src, u8* dst, int n, int idx) {
    float s = act_scale(idx);
    for (int i = blockIdx.x * blockDim.x + threadIdx.x; i < n;
         i += gridDim.x * blockDim.x)
        dst[i] = quant1(src[i], s);
}

// ---------------- conv1: qx -> h1 (relu+pool fused), maxabs -> g_amax[1] ----------------
__global__ void __launch_bounds__(288) k_conv1(const float* b1) {
    __shared__ u8 sImg[1568];      // 2 images
    __shared__ float sred[32];
    int blk = blockIdx.x, tid = threadIdx.x;
    const u32* src = (const u32*)(g_qx + (size_t)blk * 1568);
    for (int i = tid; i < 392; i += 288) ((u32*)sImg)[i] = src[i];
    __syncthreads();

    int img = tid / 144, pos = tid - img * 144;
    int py = pos / 12, px = pos - py * 12;
    float s = act_scale(0) * g_sw[0];
    float bb[6];
    #pragma unroll
    for (int o = 0; o < 6; o++) bb[o] = __ldg(b1 + o);

    float best[6] = {0, 0, 0, 0, 0, 0};   // relu outputs >= 0
    const u8* base = sImg + img * 784;
    for (int dy = 0; dy < 2; dy++) {
        for (int dx = 0; dx < 2; dx++) {
            float a0 = 0, a1 = 0, a2 = 0, a3 = 0, a4 = 0, a5 = 0;
            const u8* ip = base + (py * 2 + dy) * 28 + (px * 2 + dx);
            #pragma unroll
            for (int i = 0; i < 5; i++) {
                #pragma unroll
                for (int j = 0; j < 5; j++) {
                    int a = ip[i * 28 + j];
                    const float4* m = reinterpret_cast<const float4*>(g_M1)
                                    + (((i * 5 + j) * 256 + a) << 1);
                    float4 v0 = __ldg(m);
                    float4 v1 = __ldg(m + 1);
                    a0 += v0.x; a1 += v0.y; a2 += v0.z; a3 += v0.w;
                    a4 += v1.x; a5 += v1.y;
                }
            }
            float acc[6] = {a0, a1, a2, a3, a4, a5};
            #pragma unroll
            for (int o = 0; o < 6; o++) {
                float v = fmaxf(s * acc[o] + bb[o], 0.0f);
                best[o] = fmaxf(best[o], v);
            }
        }
    }
    int b = blk * 2 + img;
    float mymax = 0.0f;
    #pragma unroll
    for (int o = 0; o < 6; o++) {
        g_h1[(size_t)(b * 6 + o) * 144 + pos] = best[o];
        mymax = fmaxf(mymax, best[o]);
    }
    float bm = blockReduceMax(mymax, sred);
    if (tid == 0) atomicMax(&g_amax[1], __float_as_uint(bm));
}

// ---------------- conv2: qh1 -> h2 (relu+pool), maxabs -> g_amax[2] ----------------
__global__ void __launch_bounds__(256) k_conv2(const float* b2) {
    __shared__ u8 sImg[4 * 864];
    __shared__ float sVal[4 * 64 * 16];
    __shared__ float sred[32];
    int blk = blockIdx.x, tid = threadIdx.x;
    const u32* src = (const u32*)(g_qh1 + (size_t)blk * 3456);
    for (int i = tid; i < 864; i += 256) ((u32*)sImg)[i] = src[i];
    __syncthreads();

    int img = tid >> 6, pos = tid & 63;
    int y = pos >> 3, x = pos & 7;
    float acc[16];
    #pragma unroll
    for (int o = 0; o < 16; o++) acc[o] = 0.0f;

    const u8* base = sImg + img * 864 + y * 12 + x;
    for (int c = 0; c < 6; c++) {
        const u8* cp = base + c * 144;
        #pragma unroll
        for (int i = 0; i < 5; i++) {
            #pragma unroll
            for (int j = 0; j < 5; j++) {
                int ai = (int)cp[i * 12 + j] - 128;
                int k = c * 25 + i * 5 + j;
                const float4* m = reinterpret_cast<const float4*>(g_M2)
                                + ((k * 128 + ai) << 2);
                float4 v0 = __ldg(m);
                float4 v1 = __ldg(m + 1);
                float4 v2 = __ldg(m + 2);
                float4 v3 = __ldg(m + 3);
                acc[0] += v0.x;  acc[1] += v0.y;  acc[2] += v0.z;  acc[3] += v0.w;
                acc[4] += v1.x;  acc[5] += v1.y;  acc[6] += v1.z;  acc[7] += v1.w;
                acc[8] += v2.x;  acc[9] += v2.y;  acc[10] += v2.z; acc[11] += v2.w;
                acc[12] += v3.x; acc[13] += v3.y; acc[14] += v3.z; acc[15] += v3.w;
            }
        }
    }
    float s = act_scale(1) * g_sw[1];
    #pragma unroll
    for (int o = 0; o < 16; o++)
        sVal[(img * 64 + pos) * 16 + o] = fmaxf(s * acc[o] + __ldg(b2 + o), 0.0f);
    __syncthreads();

    float mymax = 0.0f;
    #pragma unroll
    for (int t = 0; t < 4; t++) {
        int id = tid + 256 * t;             // 0..1023 = 4 img * 16 pooled * 16 ch
        int im = id >> 8;
        int r = id & 255;
        int pp = r >> 4;
        int o = r & 15;
        int py = pp >> 2, px = pp & 3;
        const float* v = &sVal[(im * 64 + (py * 2) * 8 + px * 2) * 16 + o];
        float mv = fmaxf(fmaxf(v[0], v[16]), fmaxf(v[128], v[144]));
        g_h2[(size_t)(blk * 4 + im) * 256 + o * 16 + py * 4 + px] = mv;
        mymax = fmaxf(mymax, mv);
    }
    float bm = blockReduceMax(mymax, sred);
    if (tid == 0) atomicMax(&g_amax[2], __float_as_uint(bm));
}

// ---------------- fc1: qh2 -> h3, maxabs -> g_amax[3] ----------------
__global__ void __launch_bounds__(128) k_fc1(const float* fcb) {
    __shared__ u32 sq[64];
    __shared__ float sred[32];
    int b = blockIdx.x, tid = threadIdx.x;
    if (tid < 64) sq[tid] = ((const u32*)(g_qh2 + (size_t)b * 256))[tid];
    __syncthreads();
    const u8* q = (const u8*)sq;
    float acc = 0.0f;
    if (tid < 120) {
        #pragma unroll 8
        for (int k = 0; k < 256; k++) {
            int ai = (int)q[k] - 128;
            acc += __ldg(&g_M3[(size_t)(k * 128 + ai) * 120 + tid]);
        }
    }
    float s = act_scale(2) * g_sw[2];
    float val = 0.0f;
    if (tid < 120) {
        val = fmaxf(s * acc + __ldg(fcb + tid), 0.0f);
        g_h3[(size_t)b * 120 + tid] = val;
    }
    float bm = blockReduceMax(val, sred);
    if (tid == 0) atomicMax(&g_amax[3], __float_as_uint(bm));
}

// ---------------- fc2: qh3 -> h4, maxabs -> g_amax[4] ----------------
__global__ void __launch_bounds__(96) k_fc2(const float* fcb) {
    __shared__ u32 sq[30];
    __shared__ float sred[32];
    int b = blockIdx.x, tid = threadIdx.x;
    if (tid < 30) sq[tid] = ((const u32*)(g_qh3 + (size_t)b * 120))[tid];
    __syncthreads();
    const u8* q = (const u8*)sq;
    float acc = 0.0f;
    if (tid < 84) {
        #pragma unroll 8
        for (int k = 0; k < 120; k++) {
            int ai = (int)q[k] - 128;
            acc += __ldg(&g_M4[(size_t)(k * 128 + ai) * 84 + tid]);
        }
    }
    float s = act_scale(3) * g_sw[3];
    float val = 0.0f;
    if (tid < 84) {
        val = fmaxf(s * acc + __ldg(fcb + tid), 0.0f);
        g_h4[(size_t)b * 84 + tid] = val;
    }
    float bm = blockReduceMax(val, sred);
    if (tid == 0) atomicMax(&g_amax[4], __float_as_uint(bm));
}

// ---------------- fc3: qh4 -> out ----------------
__global__ void k_fc3(const float* fcb, float* out) {
    int idx = blockIdx.x * blockDim.x + threadIdx.x;
    if (idx >= BATCH * 10) return;
    int b = idx / 10, o = idx - b * 10;
    const u8* q = g_qh4 + (size_t)b * 84;
    float acc = 0.0f;
    #pragma unroll 4
    for (int k = 0; k < 84; k++) {
        int ai = (int)q[k] - 128;
        acc += __ldg(&g_M5[(k * 128 + ai) * 10 + o]);
    }
    float s = act_scale(4) * g_sw[4];
    out[idx] = s * acc + __ldg(fcb + o);
}

// ---------------- launch ----------------
extern "C" void kernel_launch(void* const* d_in, const int* in_sizes, int n_in,
                              void* d_out, int out_size) {
    const float* x   = (const float*)d_in[0];
    const float* lut = (const float*)d_in[1];
    const float* w1  = (const float*)d_in[2];
    const float* b1  = (const float*)d_in[3];
    const float* w2  = (const float*)d_in[4];
    const float* b2  = (const float*)d_in[5];
    const float* w3  = (const float*)d_in[6];
    const float* b3  = (const float*)d_in[7];
    const float* w4  = (const float*)d_in[8];
    const float* b4  = (const float*)d_in[9];
    const float* w5  = (const float*)d_in[10];
    const float* b5  = (const float*)d_in[11];
    float* out = (float*)d_out;

    float *M1p, *M2p, *M3p, *M4p, *M5p;
    u8 *qw1p, *qw2p, *qw3p, *qw4p, *qw5p;
    u8 *qxp, *qh1p, *qh2p, *qh3p, *qh4p;
    float *h1p, *h2p, *h3p, *h4p;
    cudaGetSymbolAddress((void**)&M1p, g_M1);
    cudaGetSymbolAddress((void**)&M2p, g_M2);
    cudaGetSymbolAddress((void**)&M3p, g_M3);
    cudaGetSymbolAddress((void**)&M4p, g_M4);
    cudaGetSymbolAddress((void**)&M5p, g_M5);
    cudaGetSymbolAddress((void**)&qw1p, g_qw1);
    cudaGetSymbolAddress((void**)&qw2p, g_qw2);
    cudaGetSymbolAddress((void**)&qw3p, g_qw3);
    cudaGetSymbolAddress((void**)&qw4p, g_qw4);
    cudaGetSymbolAddress((void**)&qw5p, g_qw5);
    cudaGetSymbolAddress((void**)&qxp, g_qx);
    cudaGetSymbolAddress((void**)&qh1p, g_qh1);
    cudaGetSymbolAddress((void**)&qh2p, g_qh2);
    cudaGetSymbolAddress((void**)&qh3p, g_qh3);
    cudaGetSymbolAddress((void**)&qh4p, g_qh4);
    cudaGetSymbolAddress((void**)&h1p, g_h1);
    cudaGetSymbolAddress((void**)&h2p, g_h2);
    cudaGetSymbolAddress((void**)&h3p, g_h3);
    cudaGetSymbolAddress((void**)&h4p, g_h4);

    k_zero<<<1, 32>>>();
    k_quant_w<<<5, 256>>>(w1, w2, w3, w4, w5);

    // build per-layer LUT matrices
    k_buildM<<<(25 * 256 * 8 + 255) / 256, 256>>>(M1p, qw1p, lut, 25, 6, 8, 0, 256);
    k_buildM<<<(150 * 128 * 16 + 255) / 256, 256>>>(M2p, qw2p, lut, 150, 16, 16, 128, 128);
    k_buildM<<<(256 * 128 * 120 + 255) / 256, 256>>>(M3p, qw3p, lut, 256, 120, 120, 128, 128);
    k_buildM<<<(120 * 128 * 84 + 255) / 256, 256>>>(M4p, qw4p, lut, 120, 84, 84, 128, 128);
    k_buildM<<<(84 * 128 * 10 + 255) / 256, 256>>>(M5p, qw5p, lut, 84, 10, 10, 128, 128);

    // layer 1
    int nx = BATCH * 784;
    k_maxabs<<<2048, 256>>>(x, nx, 0);
    k_quant_act<<<(nx + 255) / 256, 256>>>(x, qxp, nx, 0);
    k_conv1<<<BATCH / 2, 288>>>(b1);

    // layer 2
    int nh1 = BATCH * 6 * 144;
    k_quant_act<<<(nh1 + 255) / 256, 256>>>(h1p, qh1p, nh1, 1);
    k_conv2<<<BATCH / 4, 256>>>(b2);

    // fc1
    int nh2 = BATCH * 256;
    k_quant_act<<<(nh2 + 255) / 256, 256>>>(h2p, qh2p, nh2, 2);
    k_fc1<<<BATCH, 128>>>(b3);

    // fc2
    int nh3 = BATCH * 120;
    k_quant_act<<<(nh3 + 255) / 256, 256>>>(h3p, qh3p, nh3, 3);
    k_fc2<<<BATCH, 96>>>(b4);

    // fc3
    int nh4 = BATCH * 84;
    k_quant_act<<<(nh4 + 255) / 256, 256>>>(h4p, qh4p, nh4, 4);
    k_fc3<<<(BATCH * 10 + 255) / 256, 256>>>(b5, out);
}

// round 5
// speedup vs baseline: 1.0030x; 1.0030x over previous
#include <cuda_runtime.h>
#include <cstdint>

typedef unsigned char u8;
typedef unsigned int u32;

#define BATCH 4096

// ---------------- static device scratch (no allocations allowed) ----------------
// Per-layer LUT-matrices: M[k][a][o] = lut[a + aoff][qw[o*K + k]]
__device__ __align__(128) float g_M1[25 * 256 * 8];     // conv1: K=25, full a-range, O=6 pad 8
__device__ __align__(128) float g_M2[150 * 128 * 16];   // conv2: K=150, a in [128,255], O=16
__device__ __align__(128) float g_M3[256 * 128 * 120];  // fc1
__device__ __align__(128) float g_M4[120 * 128 * 84];   // fc2
__device__ __align__(128) float g_M5[84 * 128 * 10];    // fc3

__device__ float g_h1[BATCH * 6 * 144];
__device__ float g_h2[BATCH * 256];
__device__ float g_h3[BATCH * 120];
__device__ float g_h4[BATCH * 84];

__device__ u8 g_qw1[150], g_qw2[2400], g_qw3[30720], g_qw4[10080], g_qw5[840];
__device__ float g_sw[5];   // weight scales
__device__ u32 g_amax[5];   // activation max-abs (float bits), per layer input

// ---------------- helpers ----------------
__device__ __forceinline__ float act_scale(int i) {
    float m = __uint_as_float(g_amax[i]);
    return __fdiv_rn(m, 127.0f) + 1e-8f;
}

__device__ __forceinline__ float blockReduceMax(float v, float* sred) {
    #pragma unroll
    for (int off = 16; off; off >>= 1)
        v = fmaxf(v, __shfl_xor_sync(0xFFFFFFFFu, v, off));
    int w = threadIdx.x >> 5;
    int nw = (blockDim.x + 31) >> 5;
    if ((threadIdx.x & 31) == 0) sred[w] = v;
    __syncthreads();
    if (threadIdx.x < 32) {
        v = (threadIdx.x < nw) ? sred[threadIdx.x] : 0.0f;
        #pragma unroll
        for (int off = 16; off; off >>= 1)
            v = fmaxf(v, __shfl_xor_sync(0xFFFFFFFFu, v, off));
    }
    return v;  // valid in thread 0
}

__device__ __forceinline__ u8 quant1(float v, float s) {
    float q = rintf(__fdiv_rn(v, s));
    q = fminf(fmaxf(q, -128.0f), 127.0f);
    return (u8)((int)q + 128);
}

// ---------------- setup kernels ----------------
__global__ void k_zero() {
    if (threadIdx.x < 5) g_amax[threadIdx.x] = 0u;
}

__global__ void k_quant_w(const float* w0, const float* w1, const float* w2,
                          const float* w3, const float* w4) {
    __shared__ float sred[32];
    __shared__ float ss;
    int l = blockIdx.x;
    const float* w; int n; u8* dst;
    if      (l == 0) { w = w0; n = 150;   dst = g_qw1; }
    else if (l == 1) { w = w1; n = 2400;  dst = g_qw2; }
    else if (l == 2) { w = w2; n = 30720; dst = g_qw3; }
    else if (l == 3) { w = w3; n = 10080; dst = g_qw4; }
    else             { w = w4; n = 840;   dst = g_qw5; }
    float m = 0.0f;
    for (int i = threadIdx.x; i < n; i += blockDim.x) m = fmaxf(m, fabsf(w[i]));
    m = blockReduceMax(m, sred);
    if (threadIdx.x == 0) {
        float s = __fdiv_rn(m, 127.0f) + 1e-8f;
        g_sw[l] = s; ss = s;
    }
    __syncthreads();
    float s = ss;
    for (int i = threadIdx.x; i < n; i += blockDim.x) dst[i] = quant1(w[i], s);
}

__global__ void k_buildM(float* dst, const u8* qw, const float* lut,
                         int K, int O, int Opad, int aoff, int nA) {
    int total = K * nA * Opad;
    for (int i = blockIdx.x * blockDim.x + threadIdx.x; i < total;
         i += gridDim.x * blockDim.x) {
        int k = i / (nA * Opad);
        int r = i - k * (nA * Opad);
        int a = r / Opad;
        int o = r - a * Opad;
        dst[i] = (o < O) ? lut[(a + aoff) * 256 + (int)qw[o * K + k]] : 0.0f;
    }
}

__global__ void k_maxabs(const float* src, int n, int idx) {
    __shared__ float sred[32];
    float m = 0.0f;
    for (int i = blockIdx.x * blockDim.x + threadIdx.x; i < n;
         i += gridDim.x * blockDim.x)
        m = fmaxf(m, fabsf(src[i]));
    m = blockReduceMax(m, sred);
    if (threadIdx.x == 0) atomicMax(&g_amax[idx], __float_as_uint(m));
}

// ---------------- conv1: persistent blocks, smem-resident table ----------------
// grid=148, block=576 (4 images x 144 pooled positions), dynamic smem:
//   [0, 204800)          fp32 table, layout [k][a][8]
//   [204800, 207936)     qimg: 4 x 784 u8
//   [207936, 208064)     sred
#define C1_SMEM (204800 + 3136 + 128)

__global__ void __launch_bounds__(576, 1) k_conv1(const float* x, const float* b1) {
    extern __shared__ float smem[];
    float* tbl = smem;
    u8* qimg = (u8*)&smem[51200];
    float* sred = &smem[51200 + 784];

    int tid = threadIdx.x;
    // fill table from g_M1 (coalesced)
    {
        const float4* src = (const float4*)g_M1;
        float4* dst = (float4*)tbl;
        for (int i = tid; i < 12800; i += 576) dst[i] = src[i];
    }
    float s0 = act_scale(0);
    float sc = s0 * g_sw[0];
    float bb[6];
    #pragma unroll
    for (int o = 0; o < 6; o++) bb[o] = __ldg(b1 + o);

    int img = tid / 144, pos = tid - img * 144;
    int py = pos / 12, px = pos - py * 12;
    float mymax = 0.0f;

    for (int g = blockIdx.x; g < BATCH / 4; g += gridDim.x) {
        __syncthreads();   // table ready (iter 0) / qimg reads done (later iters)
        const float* xs = x + (size_t)g * 3136;
        for (int i = tid; i < 3136; i += 576) qimg[i] = quant1(xs[i], s0);
        __syncthreads();

        const u8* base = qimg + img * 784;
        float best[6] = {0, 0, 0, 0, 0, 0};
        #pragma unroll
        for (int dy = 0; dy < 2; dy++) {
            #pragma unroll
            for (int dx = 0; dx < 2; dx++) {
                float a0 = 0, a1 = 0, a2 = 0, a3 = 0, a4 = 0, a5 = 0;
                const u8* ip = base + (py * 2 + dy) * 28 + (px * 2 + dx);
                #pragma unroll
                for (int i = 0; i < 5; i++) {
                    #pragma unroll
                    for (int j = 0; j < 5; j++) {
                        int a = ip[i * 28 + j];
                        const float4* m = (const float4*)tbl + (((i * 5 + j) * 256 + a) << 1);
                        float4 v0 = m[0];
                        float4 v1 = m[1];
                        a0 += v0.x; a1 += v0.y; a2 += v0.z; a3 += v0.w;
                        a4 += v1.x; a5 += v1.y;
                    }
                }
                float acc[6] = {a0, a1, a2, a3, a4, a5};
                #pragma unroll
                for (int o = 0; o < 6; o++) {
                    float v = fmaxf(sc * acc[o] + bb[o], 0.0f);
                    best[o] = fmaxf(best[o], v);
                }
            }
        }
        int b = g * 4 + img;
        #pragma unroll
        for (int o = 0; o < 6; o++) {
            g_h1[(size_t)(b * 6 + o) * 144 + pos] = best[o];
            mymax = fmaxf(mymax, best[o]);
        }
    }
    float bm = blockReduceMax(mymax, sred);
    if (tid == 0) atomicMax(&g_amax[1], __float_as_uint(bm));
}

// ---------------- conv2: k-slice streaming through smem ----------------
// block = 512 threads = 8 images x 64 (pre-pool) positions; grid = 512
__global__ void __launch_bounds__(512) k_conv2(const float* b2) {
    __shared__ u8 sImg[8 * 864];
    __shared__ float4 slice[2][512];   // 2 x 8KB double buffer
    __shared__ float sred[32];

    int blk = blockIdx.x, tid = threadIdx.x;
    float s1 = act_scale(1);

    // load + quantize 8 images of h1
    const float* hsrc = g_h1 + (size_t)blk * 6912;
    for (int i = tid; i < 6912; i += 512) sImg[i] = quant1(hsrc[i], s1);

    const float4* M2 = (const float4*)g_M2;   // slice k = M2 + k*512
    slice[0][tid] = M2[tid];
    __syncthreads();

    int img = tid >> 6, pos = tid & 63;
    int y = pos >> 3, xx = pos & 7;
    const u8* ibase = sImg + img * 864 + y * 12 + xx;

    float4 A0 = {0,0,0,0}, A1 = {0,0,0,0}, A2 = {0,0,0,0}, A3 = {0,0,0,0};
    int off = 0, jc = 0, ic = 0;
    for (int k = 0; k < 150; k++) {
        float4 pre;
        if (k < 149) pre = M2[(k + 1) * 512 + tid];

        int ai = (int)ibase[off] - 128;
        const float4* row = &slice[k & 1][ai << 2];
        float4 v0 = row[0], v1 = row[1], v2 = row[2], v3 = row[3];
        A0.x += v0.x; A0.y += v0.y; A0.z += v0.z; A0.w += v0.w;
        A1.x += v1.x; A1.y += v1.y; A1.z += v1.z; A1.w += v1.w;
        A2.x += v2.x; A2.y += v2.y; A2.z += v2.z; A2.w += v2.w;
        A3.x += v3.x; A3.y += v3.y; A3.z += v3.z; A3.w += v3.w;

        // advance off over (c, i, j)
        off++; jc++;
        if (jc == 5) { jc = 0; off += 7; ic++; if (ic == 5) { ic = 0; off += 84; } }

        if (k < 149) slice[(k + 1) & 1][tid] = pre;
        __syncthreads();
    }

    // scale + bias + relu, then 2x2 pool via shuffles
    float s = s1 * g_sw[1];
    float v[16];
    {
        float acc[16] = {A0.x, A0.y, A0.z, A0.w, A1.x, A1.y, A1.z, A1.w,
                         A2.x, A2.y, A2.z, A2.w, A3.x, A3.y, A3.z, A3.w};
        #pragma unroll
        for (int o = 0; o < 16; o++)
            v[o] = fmaxf(s * acc[o] + __ldg(b2 + o), 0.0f);
    }
    #pragma unroll
    for (int o = 0; o < 16; o++) {
        v[o] = fmaxf(v[o], __shfl_xor_sync(0xFFFFFFFFu, v[o], 1));
        v[o] = fmaxf(v[o], __shfl_xor_sync(0xFFFFFFFFu, v[o], 8));
    }
    int lane = tid & 31;
    float mymax = 0.0f;
    if (!(lane & 1) && !(lane & 8)) {
        int ppy = y >> 1, ppx = xx >> 1;
        int b = blk * 8 + img;
        #pragma unroll
        for (int o = 0; o < 16; o++) {
            g_h2[(size_t)b * 256 + o * 16 + ppy * 4 + ppx] = v[o];
            mymax = fmaxf(mymax, v[o]);
        }
    }
    float bm = blockReduceMax(mymax, sred);
    if (tid == 0) atomicMax(&g_amax[2], __float_as_uint(bm));
}

// ---------------- fc1: quant-on-load, coalesced row accumulation ----------------
__global__ void __launch_bounds__(128) k_fc1(const float* fcb) {
    __shared__ u8 q[256];
    __shared__ float sred[32];
    int b = blockIdx.x, tid = threadIdx.x;
    float s2 = act_scale(2);
    for (int i = tid; i < 256; i += 128) q[i] = quant1(g_h2[(size_t)b * 256 + i], s2);
    __syncthreads();
    float acc = 0.0f;
    if (tid < 120) {
        #pragma unroll 8
        for (int k = 0; k < 256; k++) {
            int ai = (int)q[k] - 128;
            acc += __ldg(&g_M3[(size_t)(k * 128 + ai) * 120 + tid]);
        }
    }
    float s = s2 * g_sw[2];
    float val = 0.0f;
    if (tid < 120) {
        val = fmaxf(s * acc + __ldg(fcb + tid), 0.0f);
        g_h3[(size_t)b * 120 + tid] = val;
    }
    float bm = blockReduceMax(val, sred);
    if (tid == 0) atomicMax(&g_amax[3], __float_as_uint(bm));
}

// ---------------- fc2 ----------------
__global__ void __launch_bounds__(96) k_fc2(const float* fcb) {
    __shared__ u8 q[120];
    __shared__ float sred[32];
    int b = blockIdx.x, tid = threadIdx.x;
    float s3 = act_scale(3);
    for (int i = tid; i < 120; i += 96) q[i] = quant1(g_h3[(size_t)b * 120 + i], s3);
    __syncthreads();
    float acc = 0.0f;
    if (tid < 84) {
        #pragma unroll 8
        for (int k = 0; k < 120; k++) {
            int ai = (int)q[k] - 128;
            acc += __ldg(&g_M4[(size_t)(k * 128 + ai) * 84 + tid]);
        }
    }
    float s = s3 * g_sw[3];
    float val = 0.0f;
    if (tid < 84) {
        val = fmaxf(s * acc + __ldg(fcb + tid), 0.0f);
        g_h4[(size_t)b * 84 + tid] = val;
    }
    float bm = blockReduceMax(val, sred);
    if (tid == 0) atomicMax(&g_amax[4], __float_as_uint(bm));
}

// ---------------- fc3 ----------------
__global__ void __launch_bounds__(96) k_fc3(const float* fcb, float* out) {
    __shared__ u8 q[84];
    int b = blockIdx.x, tid = threadIdx.x;
    float s4 = act_scale(4);
    if (tid < 84) q[tid] = quant1(g_h4[(size_t)b * 84 + tid], s4);
    __syncthreads();
    if (tid < 10) {
        float acc = 0.0f;
        #pragma unroll 4
        for (int k = 0; k < 84; k++) {
            int ai = (int)q[k] - 128;
            acc += __ldg(&g_M5[(k * 128 + ai) * 10 + tid]);
        }
        out[b * 10 + tid] = s4 * g_sw[4] * acc + __ldg(fcb + tid);
    }
}

// ---------------- launch ----------------
extern "C" void kernel_launch(void* const* d_in, const int* in_sizes, int n_in,
                              void* d_out, int out_size) {
    const float* x   = (const float*)d_in[0];
    const float* lut = (const float*)d_in[1];
    const float* w1  = (const float*)d_in[2];
    const float* b1  = (const float*)d_in[3];
    const float* w2  = (const float*)d_in[4];
    const float* b2  = (const float*)d_in[5];
    const float* w3  = (const float*)d_in[6];
    const float* b3  = (const float*)d_in[7];
    const float* w4  = (const float*)d_in[8];
    const float* b4  = (const float*)d_in[9];
    const float* w5  = (const float*)d_in[10];
    const float* b5  = (const float*)d_in[11];
    float* out = (float*)d_out;

    float *M1p, *M2p, *M3p, *M4p, *M5p;
    u8 *qw1p, *qw2p, *qw3p, *qw4p, *qw5p;
    cudaGetSymbolAddress((void**)&M1p, g_M1);
    cudaGetSymbolAddress((void**)&M2p, g_M2);
    cudaGetSymbolAddress((void**)&M3p, g_M3);
    cudaGetSymbolAddress((void**)&M4p, g_M4);
    cudaGetSymbolAddress((void**)&M5p, g_M5);
    cudaGetSymbolAddress((void**)&qw1p, g_qw1);
    cudaGetSymbolAddress((void**)&qw2p, g_qw2);
    cudaGetSymbolAddress((void**)&qw3p, g_qw3);
    cudaGetSymbolAddress((void**)&qw4p, g_qw4);
    cudaGetSymbolAddress((void**)&qw5p, g_qw5);

    cudaFuncSetAttribute(k_conv1, cudaFuncAttributeMaxDynamicSharedMemorySize, C1_SMEM);

    k_zero<<<1, 32>>>();
    k_quant_w<<<5, 256>>>(w1, w2, w3, w4, w5);

    // build per-layer LUT matrices
    k_buildM<<<(25 * 256 * 8 + 255) / 256, 256>>>(M1p, qw1p, lut, 25, 6, 8, 0, 256);
    k_buildM<<<(150 * 128 * 16 + 255) / 256, 256>>>(M2p, qw2p, lut, 150, 16, 16, 128, 128);
    k_buildM<<<(256 * 128 * 120 + 255) / 256, 256>>>(M3p, qw3p, lut, 256, 120, 120, 128, 128);
    k_buildM<<<(120 * 128 * 84 + 255) / 256, 256>>>(M4p, qw4p, lut, 120, 84, 84, 128, 128);
    k_buildM<<<(84 * 128 * 10 + 255) / 256, 256>>>(M5p, qw5p, lut, 84, 10, 10, 128, 128);

    // input max-abs then fused pipeline
    k_maxabs<<<2048, 256>>>(x, BATCH * 784, 0);
    k_conv1<<<148, 576, C1_SMEM>>>(x, b1);
    k_conv2<<<BATCH / 8, 512>>>(b2);
    k_fc1<<<BATCH, 128>>>(b3);
    k_fc2<<<BATCH, 96>>>(b4);
    k_fc3<<<BATCH, 96>>>(b5, out);
}

// round 6
// speedup vs baseline: 1.2891x; 1.2852x over previous
#include <cuda_runtime.h>
#include <cstdint>

typedef unsigned char u8;
typedef unsigned int u32;

#define BATCH 4096

// ---------------- static device scratch (no allocations allowed) ----------------
// conv tables are stored BANK-SWIZZLED (see build kernels).
__device__ __align__(128) float g_M1[25 * 256 * 8];     // conv1, swizzled float4 halves
__device__ __align__(128) float g_M2[150 * 128 * 16];   // conv2, swizzled float4 quads
__device__ __align__(128) float g_M3[256 * 128 * 120];  // fc1 (linear)
__device__ __align__(128) float g_M4[120 * 128 * 84];   // fc2 (linear)
__device__ __align__(128) float g_M5[84 * 128 * 10];    // fc3 (linear)

__device__ float g_h1[BATCH * 6 * 144];
__device__ float g_h2[BATCH * 256];
__device__ float g_h3[BATCH * 120];
__device__ float g_h4[BATCH * 84];

__device__ u8 g_qw1[150], g_qw2[2400], g_qw3[30720], g_qw4[10080], g_qw5[840];
__device__ float g_sw[5];   // weight scales
__device__ u32 g_amax[5];   // activation max-abs (float bits), per layer input

// ---------------- helpers ----------------
__device__ __forceinline__ float act_scale(int i) {
    float m = __uint_as_float(g_amax[i]);
    return __fdiv_rn(m, 127.0f) + 1e-8f;
}

__device__ __forceinline__ float blockReduceMax(float v, float* sred) {
    #pragma unroll
    for (int off = 16; off; off >>= 1)
        v = fmaxf(v, __shfl_xor_sync(0xFFFFFFFFu, v, off));
    int w = threadIdx.x >> 5;
    int nw = (blockDim.x + 31) >> 5;
    if ((threadIdx.x & 31) == 0) sred[w] = v;
    __syncthreads();
    if (threadIdx.x < 32) {
        v = (threadIdx.x < nw) ? sred[threadIdx.x] : 0.0f;
        #pragma unroll
        for (int off = 16; off; off >>= 1)
            v = fmaxf(v, __shfl_xor_sync(0xFFFFFFFFu, v, off));
    }
    return v;  // valid in thread 0
}

__device__ __forceinline__ u8 quant1(float v, float s) {
    float q = rintf(__fdiv_rn(v, s));
    q = fminf(fmaxf(q, -128.0f), 127.0f);
    return (u8)((int)q + 128);
}

// ---------------- setup kernels ----------------
__global__ void k_quant_w(const float* w0, const float* w1, const float* w2,
                          const float* w3, const float* w4) {
    __shared__ float sred[32];
    __shared__ float ss;
    int l = blockIdx.x;
    if (l == 0 && threadIdx.x < 5) g_amax[threadIdx.x] = 0u;
    const float* w; int n; u8* dst;
    if      (l == 0) { w = w0; n = 150;   dst = g_qw1; }
    else if (l == 1) { w = w1; n = 2400;  dst = g_qw2; }
    else if (l == 2) { w = w2; n = 30720; dst = g_qw3; }
    else if (l == 3) { w = w3; n = 10080; dst = g_qw4; }
    else             { w = w4; n = 840;   dst = g_qw5; }
    float m = 0.0f;
    for (int i = threadIdx.x; i < n; i += blockDim.x) m = fmaxf(m, fabsf(w[i]));
    m = blockReduceMax(m, sred);
    if (threadIdx.x == 0) {
        float s = __fdiv_rn(m, 127.0f) + 1e-8f;
        g_sw[l] = s; ss = s;
    }
    __syncthreads();
    float s = ss;
    for (int i = threadIdx.x; i < n; i += blockDim.x) dst[i] = quant1(w[i], s);
}

// conv1 table, swizzled: float4-half h of logical row r=(k*256+a)
// lives at float4 slot 2r + (h ^ ((a>>2)&1))
__global__ void k_buildM1(const float* lut) {
    int i = blockIdx.x * blockDim.x + threadIdx.x;     // over 25*256*8
    if (i >= 25 * 256 * 8) return;
    int k = i >> 11;
    int a = (i >> 3) & 255;
    int o = i & 7;
    int h = o >> 2, c = o & 3;
    int slot = 2 * (k * 256 + a) + (h ^ ((a >> 2) & 1));
    g_M1[slot * 4 + c] = (o < 6) ? lut[a * 256 + (int)g_qw1[o * 25 + k]] : 0.0f;
}

// conv2 table, swizzled: o-quad q of row a (a = act-128, 0..127) in slice k
// lives at float4 slot 4a + ((q + a)&3); slice k occupies float4 [k*512, k*512+512)
__global__ void k_buildM2(const float* lut) {
    int i = blockIdx.x * blockDim.x + threadIdx.x;     // over 150*128*16
    if (i >= 150 * 128 * 16) return;
    int k = i >> 11;
    int a = (i >> 4) & 127;
    int o = i & 15;
    int q = o >> 2, c = o & 3;
    int slot = 4 * a + ((q + a) & 3);
    g_M2[k * 2048 + slot * 4 + c] = lut[(a + 128) * 256 + (int)g_qw2[o * 150 + k]];
}

__global__ void k_buildM(float* dst, const u8* qw, const float* lut,
                         int K, int O, int Opad, int aoff, int nA) {
    int total = K * nA * Opad;
    for (int i = blockIdx.x * blockDim.x + threadIdx.x; i < total;
         i += gridDim.x * blockDim.x) {
        int k = i / (nA * Opad);
        int r = i - k * (nA * Opad);
        int a = r / Opad;
        int o = r - a * Opad;
        dst[i] = (o < O) ? lut[(a + aoff) * 256 + (int)qw[o * K + k]] : 0.0f;
    }
}

__global__ void k_maxabs(const float* src, int n, int idx) {
    __shared__ float sred[32];
    float m = 0.0f;
    for (int i = blockIdx.x * blockDim.x + threadIdx.x; i < n;
         i += gridDim.x * blockDim.x)
        m = fmaxf(m, fabsf(src[i]));
    m = blockReduceMax(m, sred);
    if (threadIdx.x == 0) atomicMax(&g_amax[idx], __float_as_uint(m));
}

// ---------------- conv1: persistent blocks, smem-resident swizzled table ----------------
#define C1_SMEM (204800 + 3136 + 128)

__global__ void __launch_bounds__(576, 1) k_conv1(const float* x, const float* b1) {
    extern __shared__ float smem[];
    float* tbl = smem;
    u8* qimg = (u8*)&smem[51200];
    float* sred = &smem[51200 + 784];

    int tid = threadIdx.x;
    {
        const float4* src = (const float4*)g_M1;
        float4* dst = (float4*)tbl;
        for (int i = tid; i < 12800; i += 576) dst[i] = src[i];
    }
    float s0 = act_scale(0);
    float sc = s0 * g_sw[0];
    float bb[6];
    #pragma unroll
    for (int o = 0; o < 6; o++) bb[o] = __ldg(b1 + o);

    int img = tid / 144, pos = tid - img * 144;
    int py = pos / 12, px = pos - py * 12;
    float mymax = 0.0f;
    const float4* tbl4 = (const float4*)tbl;

    for (int g = blockIdx.x; g < BATCH / 4; g += gridDim.x) {
        __syncthreads();   // table ready (iter 0) / prior qimg reads done
        const float* xs = x + (size_t)g * 3136;
        for (int i = tid; i < 3136; i += 576) qimg[i] = quant1(xs[i], s0);
        __syncthreads();

        const u8* base = qimg + img * 784;
        float best[6] = {0, 0, 0, 0, 0, 0};
        #pragma unroll
        for (int dy = 0; dy < 2; dy++) {
            #pragma unroll
            for (int dx = 0; dx < 2; dx++) {
                float a0 = 0, a1 = 0, a2 = 0, a3 = 0, a4 = 0, a5 = 0;
                const u8* ip = base + (py * 2 + dy) * 28 + (px * 2 + dx);
                #pragma unroll
                for (int i = 0; i < 5; i++) {
                    #pragma unroll
                    for (int j = 0; j < 5; j++) {
                        int a = ip[i * 28 + j];
                        int r2 = ((i * 5 + j) * 256 + a) * 2;
                        int t = (a >> 2) & 1;
                        float4 v0 = tbl4[r2 + t];         // o 0-3
                        float4 v1 = tbl4[r2 + (t ^ 1)];   // o 4-7
                        a0 += v0.x; a1 += v0.y; a2 += v0.z; a3 += v0.w;
                        a4 += v1.x; a5 += v1.y;
                    }
                }
                float acc[6] = {a0, a1, a2, a3, a4, a5};
                #pragma unroll
                for (int o = 0; o < 6; o++) {
                    float v = fmaxf(sc * acc[o] + bb[o], 0.0f);
                    best[o] = fmaxf(best[o], v);
                }
            }
        }
        int b = g * 4 + img;
        #pragma unroll
        for (int o = 0; o < 6; o++) {
            g_h1[(size_t)(b * 6 + o) * 144 + pos] = best[o];
            mymax = fmaxf(mymax, best[o]);
        }
    }
    float bm = blockReduceMax(mymax, sred);
    if (tid == 0) atomicMax(&g_amax[1], __float_as_uint(bm));
}

// ---------------- conv2: 4-deep k-slice pipeline, swizzled rows ----------------
__global__ void __launch_bounds__(512) k_conv2(const float* b2) {
    __shared__ u8 sImg[8 * 864];
    __shared__ float4 slice[4][512];   // 4 x 8KB ring
    __shared__ float sred[32];

    int blk = blockIdx.x, tid = threadIdx.x;
    float s1 = act_scale(1);

    const float* hsrc = g_h1 + (size_t)blk * 6912;
    for (int i = tid; i < 6912; i += 512) sImg[i] = quant1(hsrc[i], s1);

    const float4* M2 = (const float4*)g_M2;
    #pragma unroll
    for (int s = 0; s < 4; s++) slice[s][tid] = M2[s * 512 + tid];
    __syncthreads();

    int img = tid >> 6, pos = tid & 63;
    int y = pos >> 3, xx = pos & 7;
    const u8* ibase = sImg + img * 864 + y * 12 + xx;

    float4 A0 = {0,0,0,0}, A1 = {0,0,0,0}, A2 = {0,0,0,0}, A3 = {0,0,0,0};
    int off = 0, jc = 0, ic = 0;
    for (int p = 0; p < 75; p++) {
        float4 preA, preB;
        bool more = (p < 73);
        if (more) {
            preA = M2[(2 * p + 4) * 512 + tid];
            preB = M2[(2 * p + 5) * 512 + tid];
        }
        #pragma unroll
        for (int kk = 0; kk < 2; kk++) {
            int k = 2 * p + kk;
            int ai = (int)ibase[off] - 128;
            const float4* sb = slice[k & 3];
            int rb = ai << 2;
            float4 v0 = sb[rb + ( ai      & 3)];
            float4 v1 = sb[rb + ((ai + 1) & 3)];
            float4 v2 = sb[rb + ((ai + 2) & 3)];
            float4 v3 = sb[rb + ((ai + 3) & 3)];
            A0.x += v0.x; A0.y += v0.y; A0.z += v0.z; A0.w += v0.w;
            A1.x += v1.x; A1.y += v1.y; A1.z += v1.z; A1.w += v1.w;
            A2.x += v2.x; A2.y += v2.y; A2.z += v2.z; A2.w += v2.w;
            A3.x += v3.x; A3.y += v3.y; A3.z += v3.z; A3.w += v3.w;
            off++; jc++;
            if (jc == 5) { jc = 0; off += 7; ic++; if (ic == 5) { ic = 0; off += 84; } }
        }
        __syncthreads();   // reads of bufs (2p)&3,(2p+1)&3 done
        if (more) {
            slice[(2 * p)     & 3][tid] = preA;   // slice 2p+4
            slice[(2 * p + 1) & 3][tid] = preB;   // slice 2p+5
        }
    }

    float s = s1 * g_sw[1];
    float v[16];
    {
        float acc[16] = {A0.x, A0.y, A0.z, A0.w, A1.x, A1.y, A1.z, A1.w,
                         A2.x, A2.y, A2.z, A2.w, A3.x, A3.y, A3.z, A3.w};
        #pragma unroll
        for (int o = 0; o < 16; o++)
            v[o] = fmaxf(s * acc[o] + __ldg(b2 + o), 0.0f);
    }
    #pragma unroll
    for (int o = 0; o < 16; o++) {
        v[o] = fmaxf(v[o], __shfl_xor_sync(0xFFFFFFFFu, v[o], 1));
        v[o] = fmaxf(v[o], __shfl_xor_sync(0xFFFFFFFFu, v[o], 8));
    }
    int lane = tid & 31;
    float mymax = 0.0f;
    if (!(lane & 1) && !(lane & 8)) {
        int ppy = y >> 1, ppx = xx >> 1;
        int b = blk * 8 + img;
        #pragma unroll
        for (int o = 0; o < 16; o++) {
            g_h2[(size_t)b * 256 + o * 16 + ppy * 4 + ppx] = v[o];
            mymax = fmaxf(mymax, v[o]);
        }
    }
    float bm = blockReduceMax(mymax, sred);
    if (tid == 0) atomicMax(&g_amax[2], __float_as_uint(bm));
}

// ---------------- fc1 ----------------
__global__ void __launch_bounds__(128) k_fc1(const float* fcb) {
    __shared__ u8 q[256];
    __shared__ float sred[32];
    int b = blockIdx.x, tid = threadIdx.x;
    float s2 = act_scale(2);
    for (int i = tid; i < 256; i += 128) q[i] = quant1(g_h2[(size_t)b * 256 + i], s2);
    __syncthreads();
    float acc = 0.0f;
    if (tid < 120) {
        #pragma unroll 8
        for (int k = 0; k < 256; k++) {
            int ai = (int)q[k] - 128;
            acc += __ldg(&g_M3[(size_t)(k * 128 + ai) * 120 + tid]);
        }
    }
    float s = s2 * g_sw[2];
    float val = 0.0f;
    if (tid < 120) {
        val = fmaxf(s * acc + __ldg(fcb + tid), 0.0f);
        g_h3[(size_t)b * 120 + tid] = val;
    }
    float bm = blockReduceMax(val, sred);
    if (tid == 0) atomicMax(&g_amax[3], __float_as_uint(bm));
}

// ---------------- fc2 ----------------
__global__ void __launch_bounds__(96) k_fc2(const float* fcb) {
    __shared__ u8 q[120];
    __shared__ float sred[32];
    int b = blockIdx.x, tid = threadIdx.x;
    float s3 = act_scale(3);
    for (int i = tid; i < 120; i += 96) q[i] = quant1(g_h3[(size_t)b * 120 + i], s3);
    __syncthreads();
    float acc = 0.0f;
    if (tid < 84) {
        #pragma unroll 8
        for (int k = 0; k < 120; k++) {
            int ai = (int)q[k] - 128;
            acc += __ldg(&g_M4[(size_t)(k * 128 + ai) * 84 + tid]);
        }
    }
    float s = s3 * g_sw[3];
    float val = 0.0f;
    if (tid < 84) {
        val = fmaxf(s * acc + __ldg(fcb + tid), 0.0f);
        g_h4[(size_t)b * 84 + tid] = val;
    }
    float bm = blockReduceMax(val, sred);
    if (tid == 0) atomicMax(&g_amax[4], __float_as_uint(bm));
}

// ---------------- fc3 ----------------
__global__ void __launch_bounds__(96) k_fc3(const float* fcb, float* out) {
    __shared__ u8 q[84];
    int b = blockIdx.x, tid = threadIdx.x;
    float s4 = act_scale(4);
    if (tid < 84) q[tid] = quant1(g_h4[(size_t)b * 84 + tid], s4);
    __syncthreads();
    if (tid < 10) {
        float acc = 0.0f;
        #pragma unroll 4
        for (int k = 0; k < 84; k++) {
            int ai = (int)q[k] - 128;
            acc += __ldg(&g_M5[(k * 128 + ai) * 10 + tid]);
        }
        out[b * 10 + tid] = s4 * g_sw[4] * acc + __ldg(fcb + tid);
    }
}

// ---------------- launch ----------------
extern "C" void kernel_launch(void* const* d_in, const int* in_sizes, int n_in,
                              void* d_out, int out_size) {
    const float* x   = (const float*)d_in[0];
    const float* lut = (const float*)d_in[1];
    const float* w1  = (const float*)d_in[2];
    const float* b1  = (const float*)d_in[3];
    const float* w2  = (const float*)d_in[4];
    const float* b2  = (const float*)d_in[5];
    const float* w3  = (const float*)d_in[6];
    const float* b3  = (const float*)d_in[7];
    const float* w4  = (const float*)d_in[8];
    const float* b4  = (const float*)d_in[9];
    const float* w5  = (const float*)d_in[10];
    const float* b5  = (const float*)d_in[11];
    float* out = (float*)d_out;

    float *M3p, *M4p, *M5p;
    u8 *qw3p, *qw4p, *qw5p;
    cudaGetSymbolAddress((void**)&M3p, g_M3);
    cudaGetSymbolAddress((void**)&M4p, g_M4);
    cudaGetSymbolAddress((void**)&M5p, g_M5);
    cudaGetSymbolAddress((void**)&qw3p, g_qw3);
    cudaGetSymbolAddress((void**)&qw4p, g_qw4);
    cudaGetSymbolAddress((void**)&qw5p, g_qw5);

    cudaFuncSetAttribute(k_conv1, cudaFuncAttributeMaxDynamicSharedMemorySize, C1_SMEM);

    // order chosen so ncu's -s 5 -c 1 captures a conv kernel
    k_quant_w<<<5, 256>>>(w1, w2, w3, w4, w5);                      // 1
    k_buildM1<<<(25 * 256 * 8 + 255) / 256, 256>>>(lut);            // 2
    k_buildM2<<<(150 * 128 * 16 + 255) / 256, 256>>>(lut);          // 3
    k_maxabs<<<2048, 256>>>(x, BATCH * 784, 0);                     // 4
    k_conv1<<<148, 576, C1_SMEM>>>(x, b1);                          // 5
    k_conv2<<<BATCH / 8, 512>>>(b2);                                // 6
    k_buildM<<<(256 * 128 * 120 + 255) / 256, 256>>>(M3p, qw3p, lut, 256, 120, 120, 128, 128);
    k_buildM<<<(120 * 128 * 84 + 255) / 256, 256>>>(M4p, qw4p, lut, 120, 84, 84, 128, 128);
    k_buildM<<<(84 * 128 * 10 + 255) / 256, 256>>>(M5p, qw5p, lut, 84, 10, 10, 128, 128);
    k_fc1<<<BATCH, 128>>>(b3);
    k_fc2<<<BATCH, 96>>>(b4);
    k_fc3<<<BATCH, 96>>>(b5, out);
}

// round 7
// speedup vs baseline: 1.2893x; 1.0002x over previous
#include <cuda_runtime.h>
#include <cstdint>

typedef unsigned char u8;
typedef unsigned int u32;

#define BATCH 4096

// ---------------- static device scratch (no allocations allowed) ----------------
// conv tables are stored BANK-SWIZZLED (see build kernels).
__device__ __align__(128) float g_M1[25 * 256 * 8];     // conv1, swizzled float4 halves
__device__ __align__(128) float g_M2[150 * 128 * 16];   // conv2, swizzled float4 quads
__device__ __align__(128) float g_M3[256 * 128 * 120];  // fc1 (linear)
__device__ __align__(128) float g_M4[120 * 128 * 84];   // fc2 (linear)
__device__ __align__(128) float g_M5[84 * 128 * 10];    // fc3 (linear)

__device__ float g_h1[BATCH * 6 * 144];
__device__ float g_h2[BATCH * 256];
__device__ float g_h3[BATCH * 120];
__device__ float g_h4[BATCH * 84];

__device__ u8 g_qw1[150], g_qw2[2400], g_qw3[30720], g_qw4[10080], g_qw5[840];
__device__ float g_sw[5];   // weight scales
__device__ u32 g_amax[5];   // activation max-abs (float bits), per layer input

// ---------------- helpers ----------------
__device__ __forceinline__ float act_scale(int i) {
    float m = __uint_as_float(g_amax[i]);
    return __fdiv_rn(m, 127.0f) + 1e-8f;
}

__device__ __forceinline__ float blockReduceMax(float v, float* sred) {
    #pragma unroll
    for (int off = 16; off; off >>= 1)
        v = fmaxf(v, __shfl_xor_sync(0xFFFFFFFFu, v, off));
    int w = threadIdx.x >> 5;
    int nw = (blockDim.x + 31) >> 5;
    if ((threadIdx.x & 31) == 0) sred[w] = v;
    __syncthreads();
    if (threadIdx.x < 32) {
        v = (threadIdx.x < nw) ? sred[threadIdx.x] : 0.0f;
        #pragma unroll
        for (int off = 16; off; off >>= 1)
            v = fmaxf(v, __shfl_xor_sync(0xFFFFFFFFu, v, off));
    }
    return v;  // valid in thread 0
}

__device__ __forceinline__ u8 quant1(float v, float s) {
    float q = rintf(__fdiv_rn(v, s));
    q = fminf(fmaxf(q, -128.0f), 127.0f);
    return (u8)((int)q + 128);
}

// ---------------- setup kernels ----------------
__global__ void k_quant_w(const float* w0, const float* w1, const float* w2,
                          const float* w3, const float* w4) {
    __shared__ float sred[32];
    __shared__ float ss;
    int l = blockIdx.x;
    if (l == 0 && threadIdx.x < 5) g_amax[threadIdx.x] = 0u;
    const float* w; int n; u8* dst;
    if      (l == 0) { w = w0; n = 150;   dst = g_qw1; }
    else if (l == 1) { w = w1; n = 2400;  dst = g_qw2; }
    else if (l == 2) { w = w2; n = 30720; dst = g_qw3; }
    else if (l == 3) { w = w3; n = 10080; dst = g_qw4; }
    else             { w = w4; n = 840;   dst = g_qw5; }
    float m = 0.0f;
    for (int i = threadIdx.x; i < n; i += blockDim.x) m = fmaxf(m, fabsf(w[i]));
    m = blockReduceMax(m, sred);
    if (threadIdx.x == 0) {
        float s = __fdiv_rn(m, 127.0f) + 1e-8f;
        g_sw[l] = s; ss = s;
    }
    __syncthreads();
    float s = ss;
    for (int i = threadIdx.x; i < n; i += blockDim.x) dst[i] = quant1(w[i], s);
}

// conv1 table, swizzled: float4-half h of logical row r=(k*256+a)
// lives at float4 slot 2r + (h ^ ((a>>2)&1))
__global__ void k_buildM1(const float* lut) {
    int i = blockIdx.x * blockDim.x + threadIdx.x;     // over 25*256*8
    if (i >= 25 * 256 * 8) return;
    int k = i >> 11;
    int a = (i >> 3) & 255;
    int o = i & 7;
    int h = o >> 2, c = o & 3;
    int slot = 2 * (k * 256 + a) + (h ^ ((a >> 2) & 1));
    g_M1[slot * 4 + c] = (o < 6) ? lut[a * 256 + (int)g_qw1[o * 25 + k]] : 0.0f;
}

// conv2 table, swizzled: o-quad q of row a (a = act-128, 0..127) in slice k
// lives at float4 slot 4a + ((q + a)&3); slice k occupies float4 [k*512, k*512+512)
__global__ void k_buildM2(const float* lut) {
    int i = blockIdx.x * blockDim.x + threadIdx.x;     // over 150*128*16
    if (i >= 150 * 128 * 16) return;
    int k = i >> 11;
    int a = (i >> 4) & 127;
    int o = i & 15;
    int q = o >> 2, c = o & 3;
    int slot = 4 * a + ((q + a) & 3);
    g_M2[k * 2048 + slot * 4 + c] = lut[(a + 128) * 256 + (int)g_qw2[o * 150 + k]];
}

__global__ void k_buildM(float* dst, const u8* qw, const float* lut,
                         int K, int O, int Opad, int aoff, int nA) {
    int total = K * nA * Opad;
    for (int i = blockIdx.x * blockDim.x + threadIdx.x; i < total;
         i += gridDim.x * blockDim.x) {
        int k = i / (nA * Opad);
        int r = i - k * (nA * Opad);
        int a = r / Opad;
        int o = r - a * Opad;
        dst[i] = (o < O) ? lut[(a + aoff) * 256 + (int)qw[o * K + k]] : 0.0f;
    }
}

__global__ void k_maxabs(const float* src, int n, int idx) {
    __shared__ float sred[32];
    float m = 0.0f;
    for (int i = blockIdx.x * blockDim.x + threadIdx.x; i < n;
         i += gridDim.x * blockDim.x)
        m = fmaxf(m, fabsf(src[i]));
    m = blockReduceMax(m, sred);
    if (threadIdx.x == 0) atomicMax(&g_amax[idx], __float_as_uint(m));
}

// ---------------- conv1: persistent blocks, smem-resident swizzled table ----------------
#define C1_SMEM (204800 + 3136 + 128)

__global__ void __launch_bounds__(576, 1) k_conv1(const float* x, const float* b1) {
    extern __shared__ float smem[];
    float* tbl = smem;
    u8* qimg = (u8*)&smem[51200];
    float* sred = &smem[51200 + 784];

    int tid = threadIdx.x;
    {
        const float4* src = (const float4*)g_M1;
        float4* dst = (float4*)tbl;
        for (int i = tid; i < 12800; i += 576) dst[i] = src[i];
    }
    float s0 = act_scale(0);
    float sc = s0 * g_sw[0];
    float bb[6];
    #pragma unroll
    for (int o = 0; o < 6; o++) bb[o] = __ldg(b1 + o);

    int img = tid / 144, pos = tid - img * 144;
    int py = pos / 12, px = pos - py * 12;
    float mymax = 0.0f;
    const float4* tbl4 = (const float4*)tbl;

    for (int g = blockIdx.x; g < BATCH / 4; g += gridDim.x) {
        __syncthreads();   // table ready (iter 0) / prior qimg reads done
        const float* xs = x + (size_t)g * 3136;
        for (int i = tid; i < 3136; i += 576) qimg[i] = quant1(xs[i], s0);
        __syncthreads();

        const u8* base = qimg + img * 784;
        float best[6] = {0, 0, 0, 0, 0, 0};
        #pragma unroll
        for (int dy = 0; dy < 2; dy++) {
            #pragma unroll
            for (int dx = 0; dx < 2; dx++) {
                float a0 = 0, a1 = 0, a2 = 0, a3 = 0, a4 = 0, a5 = 0;
                const u8* ip = base + (py * 2 + dy) * 28 + (px * 2 + dx);
                #pragma unroll
                for (int i = 0; i < 5; i++) {
                    #pragma unroll
                    for (int j = 0; j < 5; j++) {
                        int a = ip[i * 28 + j];
                        int r2 = ((i * 5 + j) * 256 + a) * 2;
                        int t = (a >> 2) & 1;
                        float4 v0 = tbl4[r2 + t];         // o 0-3
                        float4 v1 = tbl4[r2 + (t ^ 1)];   // o 4-7
                        a0 += v0.x; a1 += v0.y; a2 += v0.z; a3 += v0.w;
                        a4 += v1.x; a5 += v1.y;
                    }
                }
                float acc[6] = {a0, a1, a2, a3, a4, a5};
                #pragma unroll
                for (int o = 0; o < 6; o++) {
                    float v = fmaxf(sc * acc[o] + bb[o], 0.0f);
                    best[o] = fmaxf(best[o], v);
                }
            }
        }
        int b = g * 4 + img;
        #pragma unroll
        for (int o = 0; o < 6; o++) {
            g_h1[(size_t)(b * 6 + o) * 144 + pos] = best[o];
            mymax = fmaxf(mymax, best[o]);
        }
    }
    float bm = blockReduceMax(mymax, sred);
    if (tid == 0) atomicMax(&g_amax[1], __float_as_uint(bm));
}

// ---------------- conv2: 4-deep k-slice pipeline, swizzled rows ----------------
__global__ void __launch_bounds__(512) k_conv2(const float* b2) {
    __shared__ u8 sImg[8 * 864];
    __shared__ float4 slice[4][512];   // 4 x 8KB ring
    __shared__ float sred[32];

    int blk = blockIdx.x, tid = threadIdx.x;
    float s1 = act_scale(1);

    const float* hsrc = g_h1 + (size_t)blk * 6912;
    for (int i = tid; i < 6912; i += 512) sImg[i] = quant1(hsrc[i], s1);

    const float4* M2 = (const float4*)g_M2;
    #pragma unroll
    for (int s = 0; s < 4; s++) slice[s][tid] = M2[s * 512 + tid];
    __syncthreads();

    int img = tid >> 6, pos = tid & 63;
    int y = pos >> 3, xx = pos & 7;
    const u8* ibase = sImg + img * 864 + y * 12 + xx;

    float4 A0 = {0,0,0,0}, A1 = {0,0,0,0}, A2 = {0,0,0,0}, A3 = {0,0,0,0};
    int off = 0, jc = 0, ic = 0;
    for (int p = 0; p < 75; p++) {
        float4 preA, preB;
        bool more = (p < 73);
        if (more) {
            preA = M2[(2 * p + 4) * 512 + tid];
            preB = M2[(2 * p + 5) * 512 + tid];
        }
        #pragma unroll
        for (int kk = 0; kk < 2; kk++) {
            int k = 2 * p + kk;
            int ai = (int)ibase[off] - 128;
            const float4* sb = slice[k & 3];
            int rb = ai << 2;
            float4 v0 = sb[rb + ( ai      & 3)];
            float4 v1 = sb[rb + ((ai + 1) & 3)];
            float4 v2 = sb[rb + ((ai + 2) & 3)];
            float4 v3 = sb[rb + ((ai + 3) & 3)];
            A0.x += v0.x; A0.y += v0.y; A0.z += v0.z; A0.w += v0.w;
            A1.x += v1.x; A1.y += v1.y; A1.z += v1.z; A1.w += v1.w;
            A2.x += v2.x; A2.y += v2.y; A2.z += v2.z; A2.w += v2.w;
            A3.x += v3.x; A3.y += v3.y; A3.z += v3.z; A3.w += v3.w;
            off++; jc++;
            if (jc == 5) { jc = 0; off += 7; ic++; if (ic == 5) { ic = 0; off += 84; } }
        }
        __syncthreads();   // reads of bufs (2p)&3,(2p+1)&3 done
        if (more) {
            slice[(2 * p)     & 3][tid] = preA;   // slice 2p+4
            slice[(2 * p + 1) & 3][tid] = preB;   // slice 2p+5
        }
    }

    float s = s1 * g_sw[1];
    float v[16];
    {
        float acc[16] = {A0.x, A0.y, A0.z, A0.w, A1.x, A1.y, A1.z, A1.w,
                         A2.x, A2.y, A2.z, A2.w, A3.x, A3.y, A3.z, A3.w};
        #pragma unroll
        for (int o = 0; o < 16; o++)
            v[o] = fmaxf(s * acc[o] + __ldg(b2 + o), 0.0f);
    }
    #pragma unroll
    for (int o = 0; o < 16; o++) {
        v[o] = fmaxf(v[o], __shfl_xor_sync(0xFFFFFFFFu, v[o], 1));
        v[o] = fmaxf(v[o], __shfl_xor_sync(0xFFFFFFFFu, v[o], 8));
    }
    int lane = tid & 31;
    float mymax = 0.0f;
    if (!(lane & 1) && !(lane & 8)) {
        int ppy = y >> 1, ppx = xx >> 1;
        int b = blk * 8 + img;
        #pragma unroll
        for (int o = 0; o < 16; o++) {
            g_h2[(size_t)b * 256 + o * 16 + ppy * 4 + ppx] = v[o];
            mymax = fmaxf(mymax, v[o]);
        }
    }
    float bm = blockReduceMax(mymax, sred);
    if (tid == 0) atomicMax(&g_amax[2], __float_as_uint(bm));
}

// ---------------- fc1 ----------------
__global__ void __launch_bounds__(128) k_fc1(const float* fcb) {
    __shared__ u8 q[256];
    __shared__ float sred[32];
    int b = blockIdx.x, tid = threadIdx.x;
    float s2 = act_scale(2);
    for (int i = tid; i < 256; i += 128) q[i] = quant1(g_h2[(size_t)b * 256 + i], s2);
    __syncthreads();
    float acc = 0.0f;
    if (tid < 120) {
        #pragma unroll 8
        for (int k = 0; k < 256; k++) {
            int ai = (int)q[k] - 128;
            acc += __ldg(&g_M3[(size_t)(k * 128 + ai) * 120 + tid]);
        }
    }
    float s = s2 * g_sw[2];
    float val = 0.0f;
    if (tid < 120) {
        val = fmaxf(s * acc + __ldg(fcb + tid), 0.0f);
        g_h3[(size_t)b * 120 + tid] = val;
    }
    float bm = blockReduceMax(val, sred);
    if (tid == 0) atomicMax(&g_amax[3], __float_as_uint(bm));
}

// ---------------- fc2 ----------------
__global__ void __launch_bounds__(96) k_fc2(const float* fcb) {
    __shared__ u8 q[120];
    __shared__ float sred[32];
    int b = blockIdx.x, tid = threadIdx.x;
    float s3 = act_scale(3);
    for (int i = tid; i < 120; i += 96) q[i] = quant1(g_h3[(size_t)b * 120 + i], s3);
    __syncthreads();
    float acc = 0.0f;
    if (tid < 84) {
        #pragma unroll 8
        for (int k = 0; k < 120; k++) {
            int ai = (int)q[k] - 128;
            acc += __ldg(&g_M4[(size_t)(k * 128 + ai) * 84 + tid]);
        }
    }
    float s = s3 * g_sw[3];
    float val = 0.0f;
    if (tid < 84) {
        val = fmaxf(s * acc + __ldg(fcb + tid), 0.0f);
        g_h4[(size_t)b * 84 + tid] = val;
    }
    float bm = blockReduceMax(val, sred);
    if (tid == 0) atomicMax(&g_amax[4], __float_as_uint(bm));
}

// ---------------- fc3 ----------------
__global__ void __launch_bounds__(96) k_fc3(const float* fcb, float* out) {
    __shared__ u8 q[84];
    int b = blockIdx.x, tid = threadIdx.x;
    float s4 = act_scale(4);
    if (tid < 84) q[tid] = quant1(g_h4[(size_t)b * 84 + tid], s4);
    __syncthreads();
    if (tid < 10) {
        float acc = 0.0f;
        #pragma unroll 4
        for (int k = 0; k < 84; k++) {
            int ai = (int)q[k] - 128;
            acc += __ldg(&g_M5[(k * 128 + ai) * 10 + tid]);
        }
        out[b * 10 + tid] = s4 * g_sw[4] * acc + __ldg(fcb + tid);
    }
}

// ---------------- launch ----------------
extern "C" void kernel_launch(void* const* d_in, const int* in_sizes, int n_in,
                              void* d_out, int out_size) {
    const float* x   = (const float*)d_in[0];
    const float* lut = (const float*)d_in[1];
    const float* w1  = (const float*)d_in[2];
    const float* b1  = (const float*)d_in[3];
    const float* w2  = (const float*)d_in[4];
    const float* b2  = (const float*)d_in[5];
    const float* w3  = (const float*)d_in[6];
    const float* b3  = (const float*)d_in[7];
    const float* w4  = (const float*)d_in[8];
    const float* b4  = (const float*)d_in[9];
    const float* w5  = (const float*)d_in[10];
    const float* b5  = (const float*)d_in[11];
    float* out = (float*)d_out;

    float *M3p, *M4p, *M5p;
    u8 *qw3p, *qw4p, *qw5p;
    cudaGetSymbolAddress((void**)&M3p, g_M3);
    cudaGetSymbolAddress((void**)&M4p, g_M4);
    cudaGetSymbolAddress((void**)&M5p, g_M5);
    cudaGetSymbolAddress((void**)&qw3p, g_qw3);
    cudaGetSymbolAddress((void**)&qw4p, g_qw4);
    cudaGetSymbolAddress((void**)&qw5p, g_qw5);

    cudaFuncSetAttribute(k_conv1, cudaFuncAttributeMaxDynamicSharedMemorySize, C1_SMEM);

    // order chosen so ncu's -s 5 -c 1 captures a conv kernel
    k_quant_w<<<5, 256>>>(w1, w2, w3, w4, w5);                      // 1
    k_buildM1<<<(25 * 256 * 8 + 255) / 256, 256>>>(lut);            // 2
    k_buildM2<<<(150 * 128 * 16 + 255) / 256, 256>>>(lut);          // 3
    k_maxabs<<<2048, 256>>>(x, BATCH * 784, 0);                     // 4
    k_conv1<<<148, 576, C1_SMEM>>>(x, b1);                          // 5
    k_conv2<<<BATCH / 8, 512>>>(b2);                                // 6
    k_buildM<<<(256 * 128 * 120 + 255) / 256, 256>>>(M3p, qw3p, lut, 256, 120, 120, 128, 128);
    k_buildM<<<(120 * 128 * 84 + 255) / 256, 256>>>(M4p, qw4p, lut, 120, 84, 84, 128, 128);
    k_buildM<<<(84 * 128 * 10 + 255) / 256, 256>>>(M5p, qw5p, lut, 84, 10, 10, 128, 128);
    k_fc1<<<BATCH, 128>>>(b3);
    k_fc2<<<BATCH, 96>>>(b4);
    k_fc3<<<BATCH, 96>>>(b5, out);
}

// round 9
// speedup vs baseline: 1.4854x; 1.1521x over previous
#include <cuda_runtime.h>
#include <cuda_fp16.h>
#include <cstdint>

typedef unsigned char u8;
typedef unsigned int u32;

#define BATCH 4096

// ---------------- static device scratch ----------------
__device__ __align__(128) float g_M1[25 * 256 * 8];     // conv1, swizzled float4 halves
__device__ __align__(16)  __half g_R2[150 * 128 * 16];  // conv2 fp16 residuals, unit-swizzled
__device__ __align__(128) float g_M3[256 * 128 * 120];  // fc1
__device__ __align__(128) float g_M4[120 * 128 * 84];   // fc2
__device__ __align__(128) float g_M5[84 * 128 * 10];    // fc3

__device__ float g_h1[BATCH * 6 * 144];
__device__ float g_h2[BATCH * 256];
__device__ float g_h3[BATCH * 120];
__device__ float g_h4[BATCH * 84];

__device__ u8 g_qw1[150], g_qw2[2400], g_qw3[30720], g_qw4[10080], g_qw5[840];
__device__ __align__(16) u32 g_pw2[1152];   // conv2 packed signed weights [o=16][c=6][12 words]
__device__ float g_sw[5];
__device__ u32 g_amax[5];

// ---------------- helpers ----------------
__device__ __forceinline__ float act_scale(int i) {
    float m = __uint_as_float(g_amax[i]);
    return __fdiv_rn(m, 127.0f) + 1e-8f;
}

__device__ __forceinline__ float blockReduceMax(float v, float* sred) {
    #pragma unroll
    for (int off = 16; off; off >>= 1)
        v = fmaxf(v, __shfl_xor_sync(0xFFFFFFFFu, v, off));
    int w = threadIdx.x >> 5;
    int nw = (blockDim.x + 31) >> 5;
    if ((threadIdx.x & 31) == 0) sred[w] = v;
    __syncthreads();
    if (threadIdx.x < 32) {
        v = (threadIdx.x < nw) ? sred[threadIdx.x] : 0.0f;
        #pragma unroll
        for (int off = 16; off; off >>= 1)
            v = fmaxf(v, __shfl_xor_sync(0xFFFFFFFFu, v, off));
    }
    return v;
}

__device__ __forceinline__ u8 quant1(float v, float s) {
    float q = rintf(__fdiv_rn(v, s));
    q = fminf(fmaxf(q, -128.0f), 127.0f);
    return (u8)((int)q + 128);
}

// ---------------- setup kernels ----------------
__global__ void k_quant_w(const float* w0, const float* w1, const float* w2,
                          const float* w3, const float* w4) {
    __shared__ float sred[32];
    __shared__ float ss;
    int l = blockIdx.x;
    if (l == 0 && threadIdx.x < 5) g_amax[threadIdx.x] = 0u;
    const float* w; int n; u8* dst;
    if      (l == 0) { w = w0; n = 150;   dst = g_qw1; }
    else if (l == 1) { w = w1; n = 2400;  dst = g_qw2; }
    else if (l == 2) { w = w2; n = 30720; dst = g_qw3; }
    else if (l == 3) { w = w3; n = 10080; dst = g_qw4; }
    else             { w = w4; n = 840;   dst = g_qw5; }
    float m = 0.0f;
    for (int i = threadIdx.x; i < n; i += blockDim.x) m = fmaxf(m, fabsf(w[i]));
    m = blockReduceMax(m, sred);
    if (threadIdx.x == 0) {
        float s = __fdiv_rn(m, 127.0f) + 1e-8f;
        g_sw[l] = s; ss = s;
    }
    __syncthreads();
    float s = ss;
    for (int i = threadIdx.x; i < n; i += blockDim.x) dst[i] = quant1(w[i], s);
    if (l == 1) {   // pack conv2 signed weights for dp4a: [o][c][12 words]
        __syncthreads();
        for (int t = threadIdx.x; t < 1152; t += blockDim.x) {
            int o = t / 72, rem = t % 72, c = rem / 12, w12 = rem % 12;
            u32 word = 0;
            if (w12 < 10) {
                int i = w12 >> 1;
                #pragma unroll
                for (int bt = 0; bt < 4; bt++) {
                    int j = (w12 & 1) * 4 + bt;
                    if (j < 5)
                        word |= (u32)(u8)(g_qw2[o * 150 + c * 25 + i * 5 + j] ^ 0x80) << (8 * bt);
                }
            }
            g_pw2[t] = word;
        }
    }
}

// conv1 table, swizzled: float4-half h of row r=(k*256+a) at slot 2r + (h ^ ((a>>2)&1))
__global__ void k_buildM1(const float* lut) {
    int i = blockIdx.x * blockDim.x + threadIdx.x;
    if (i >= 25 * 256 * 8) return;
    int k = i >> 11, a = (i >> 3) & 255, o = i & 7;
    int h = o >> 2, c = o & 3;
    int slot = 2 * (k * 256 + a) + (h ^ ((a >> 2) & 1));
    g_M1[slot * 4 + c] = (o < 6) ? lut[a * 256 + (int)g_qw1[o * 25 + k]] : 0.0f;
}

// conv2 residual: r = lut[(a+128)][qw] - a*(qw-128); half h (o0-7/o8-15) of row a in
// slice k stored at 16B unit 2a + (h ^ (a&1))
__global__ void k_buildR2(const float* lut) {
    int i = blockIdx.x * blockDim.x + threadIdx.x;
    if (i >= 150 * 128 * 16) return;
    int k = i >> 11, a = (i >> 4) & 127, o = i & 15;
    int qwi = g_qw2[o * 150 + k];
    float v = lut[(a + 128) * 256 + qwi] - (float)(a * (qwi - 128));
    int unit = 2 * a + ((o >> 3) ^ (a & 1));
    g_R2[k * 2048 + unit * 8 + (o & 7)] = __float2half_rn(v);
}

__global__ void k_buildM(float* dst, const u8* qw, const float* lut,
                         int K, int O, int Opad, int aoff, int nA) {
    int total = K * nA * Opad;
    for (int i = blockIdx.x * blockDim.x + threadIdx.x; i < total;
         i += gridDim.x * blockDim.x) {
        int k = i / (nA * Opad);
        int r = i - k * (nA * Opad);
        int a = r / Opad;
        int o = r - a * Opad;
        dst[i] = (o < O) ? lut[(a + aoff) * 256 + (int)qw[o * K + k]] : 0.0f;
    }
}

__global__ void k_maxabs(const float* src, int n, int idx) {
    __shared__ float sred[32];
    float m = 0.0f;
    for (int i = blockIdx.x * blockDim.x + threadIdx.x; i < n;
         i += gridDim.x * blockDim.x)
        m = fmaxf(m, fabsf(src[i]));
    m = blockReduceMax(m, sred);
    if (threadIdx.x == 0) atomicMax(&g_amax[idx], __float_as_uint(m));
}

// ---------------- conv1: persistent blocks, smem-resident swizzled table ----------------
#define C1_SMEM (204800 + 3136 + 128)

__global__ void __launch_bounds__(576, 1) k_conv1(const float* x, const float* b1) {
    extern __shared__ float smem[];
    float* tbl = smem;
    u8* qimg = (u8*)&smem[51200];
    float* sred = &smem[51200 + 784];

    int tid = threadIdx.x;
    {
        const float4* src = (const float4*)g_M1;
        float4* dst = (float4*)tbl;
        for (int i = tid; i < 12800; i += 576) dst[i] = src[i];
    }
    float s0 = act_scale(0);
    float sc = s0 * g_sw[0];
    float bb[6];
    #pragma unroll
    for (int o = 0; o < 6; o++) bb[o] = __ldg(b1 + o);

    int img = tid / 144, pos = tid - img * 144;
    int py = pos / 12, px = pos - py * 12;
    float mymax = 0.0f;
    const float4* tbl4 = (const float4*)tbl;

    for (int g = blockIdx.x; g < BATCH / 4; g += gridDim.x) {
        __syncthreads();
        const float* xs = x + (size_t)g * 3136;
        for (int i = tid; i < 3136; i += 576) qimg[i] = quant1(xs[i], s0);
        __syncthreads();

        const u8* base = qimg + img * 784;
        float best[6] = {0, 0, 0, 0, 0, 0};
        #pragma unroll
        for (int dy = 0; dy < 2; dy++) {
            #pragma unroll
            for (int dx = 0; dx < 2; dx++) {
                float a0 = 0, a1 = 0, a2 = 0, a3 = 0, a4 = 0, a5 = 0;
                const u8* ip = base + (py * 2 + dy) * 28 + (px * 2 + dx);
                #pragma unroll
                for (int i = 0; i < 5; i++) {
                    #pragma unroll
                    for (int j = 0; j < 5; j++) {
                        int a = ip[i * 28 + j];
                        int r2 = ((i * 5 + j) * 256 + a) * 2;
                        int t = (a >> 2) & 1;
                        float4 v0 = tbl4[r2 + t];
                        float4 v1 = tbl4[r2 + (t ^ 1)];
                        a0 += v0.x; a1 += v0.y; a2 += v0.z; a3 += v0.w;
                        a4 += v1.x; a5 += v1.y;
                    }
                }
                float acc[6] = {a0, a1, a2, a3, a4, a5};
                #pragma unroll
                for (int o = 0; o < 6; o++) {
                    float v = fmaxf(sc * acc[o] + bb[o], 0.0f);
                    best[o] = fmaxf(best[o], v);
                }
            }
        }
        int b = g * 4 + img;
        #pragma unroll
        for (int o = 0; o < 6; o++) {
            g_h1[(size_t)(b * 6 + o) * 144 + pos] = best[o];
            mymax = fmaxf(mymax, best[o]);
        }
    }
    float bm = blockReduceMax(mymax, sred);
    if (tid == 0) atomicMax(&g_amax[1], __float_as_uint(bm));
}

// ---------------- conv2: dp4a exact int + fp16 residual (chunk-flushed to fp32) ----------------
__global__ void __launch_bounds__(512) k_conv2(const float* b2) {
    __shared__ __align__(16) u8 sImg[8 * 864 + 16];
    __shared__ uint4 ring[4][256];     // 4 x 4KB residual slices
    __shared__ float sred[32];

    int blk = blockIdx.x, tid = threadIdx.x;
    float s1 = act_scale(1);

    const float* hsrc = g_h1 + (size_t)blk * 6912;
    for (int i = tid; i < 6912; i += 512) sImg[i] = quant1(hsrc[i], s1) ^ 0x80; // ai in [0,127]
    if (tid < 16) sImg[6912 + tid] = 0;

    const uint4* R2 = (const uint4*)g_R2;     // slice k = [k*256, +256)
    int ss = tid >> 8, rr = tid & 255;
    ring[ss][rr] = R2[ss * 256 + rr];
    ring[ss + 2][rr] = R2[(ss + 2) * 256 + rr];
    __syncthreads();

    int img = tid >> 6, pos = tid & 63;
    int y = pos >> 3, xx = pos & 7;
    int base0 = img * 864 + y * 12 + xx;
    const u32* qword = (const u32*)sImg;

    // phase 1: exact integer part via dp4a
    int acc[16];
    #pragma unroll
    for (int o = 0; o < 16; o++) acc[o] = 0;
    #pragma unroll
    for (int c = 0; c < 6; c++) {
        u32 qa[10];
        #pragma unroll
        for (int i2 = 0; i2 < 5; i2++) {
            int boff = base0 + c * 144 + i2 * 12;
            u32 w0 = qword[boff >> 2], w1 = qword[(boff >> 2) + 1];
            int sh = (boff & 3) * 8;
            qa[i2 * 2]     = __funnelshift_r(w0, w1, sh);
            qa[i2 * 2 + 1] = (w1 >> sh) & 0xFF;
        }
        #pragma unroll
        for (int o = 0; o < 16; o++) {
            const uint4* pwo = (const uint4*)g_pw2 + (o * 6 + c) * 3;
            uint4 A = __ldg(pwo), B = __ldg(pwo + 1), C = __ldg(pwo + 2);
            int a = acc[o];
            a = __dp4a((int)qa[0], (int)A.x, a);
            a = __dp4a((int)qa[1], (int)A.y, a);
            a = __dp4a((int)qa[2], (int)A.z, a);
            a = __dp4a((int)qa[3], (int)A.w, a);
            a = __dp4a((int)qa[4], (int)B.x, a);
            a = __dp4a((int)qa[5], (int)B.y, a);
            a = __dp4a((int)qa[6], (int)B.z, a);
            a = __dp4a((int)qa[7], (int)B.w, a);
            a = __dp4a((int)qa[8], (int)C.x, a);
            a = __dp4a((int)qa[9], (int)C.y, a);
            acc[o] = a;
        }
    }

    // phase 2: fp16 residual, k-major slice streaming; flush to fp32 every 16 p (32 k)
    float facc[16];
    #pragma unroll
    for (int o = 0; o < 16; o++) facc[o] = 0.0f;
    __half2 rh[8];
    #pragma unroll
    for (int j = 0; j < 8; j++) rh[j] = __float2half2_rn(0.0f);

    const u8* ibase = sImg + base0;
    int off = 0, jc = 0, ic = 0;
    for (int p = 0; p < 75; p++) {
        uint4 pre;
        bool more = (p < 73);
        if (more) pre = R2[(2 * p + 4 + ss) * 256 + rr];
        #pragma unroll
        for (int kk = 0; kk < 2; kk++) {
            int k = 2 * p + kk;
            int ai = ibase[off];
            const uint4* sb = ring[k & 3];
            int t = ai & 1;
            uint4 u0 = sb[2 * ai + t];
            uint4 u1 = sb[2 * ai + (t ^ 1)];
            const __half2* h0 = (const __half2*)&u0;
            const __half2* h1 = (const __half2*)&u1;
            rh[0] = __hadd2(rh[0], h0[0]); rh[1] = __hadd2(rh[1], h0[1]);
            rh[2] = __hadd2(rh[2], h0[2]); rh[3] = __hadd2(rh[3], h0[3]);
            rh[4] = __hadd2(rh[4], h1[0]); rh[5] = __hadd2(rh[5], h1[1]);
            rh[6] = __hadd2(rh[6], h1[2]); rh[7] = __hadd2(rh[7], h1[3]);
            off++; jc++;
            if (jc == 5) { jc = 0; off += 7; ic++; if (ic == 5) { ic = 0; off += 84; } }
        }
        __syncthreads();
        if (more) ring[(2 * p + ss) & 3][rr] = pre;   // slice 2p+4+ss
        if ((p & 15) == 15) {   // chunk flush: keep fp16 walk short
            #pragma unroll
            for (int j = 0; j < 8; j++) {
                float2 f = __half22float2(rh[j]);
                facc[2 * j]     += f.x;
                facc[2 * j + 1] += f.y;
                rh[j] = __float2half2_rn(0.0f);
            }
        }
    }
    #pragma unroll
    for (int j = 0; j < 8; j++) {   // final flush
        float2 f = __half22float2(rh[j]);
        facc[2 * j]     += f.x;
        facc[2 * j + 1] += f.y;
    }

    float s = s1 * g_sw[1];
    float v[16];
    #pragma unroll
    for (int o = 0; o < 16; o++)
        v[o] = fmaxf(s * ((float)acc[o] + facc[o]) + __ldg(b2 + o), 0.0f);

    #pragma unroll
    for (int o = 0; o < 16; o++) {
        v[o] = fmaxf(v[o], __shfl_xor_sync(0xFFFFFFFFu, v[o], 1));
        v[o] = fmaxf(v[o], __shfl_xor_sync(0xFFFFFFFFu, v[o], 8));
    }
    int lane = tid & 31;
    float mymax = 0.0f;
    if (!(lane & 1) && !(lane & 8)) {
        int ppy = y >> 1, ppx = xx >> 1;
        int b = blk * 8 + img;
        #pragma unroll
        for (int o = 0; o < 16; o++) {
            g_h2[(size_t)b * 256 + o * 16 + ppy * 4 + ppx] = v[o];
            mymax = fmaxf(mymax, v[o]);
        }
    }
    float bm = blockReduceMax(mymax, sred);
    if (tid == 0) atomicMax(&g_amax[2], __float_as_uint(bm));
}

// ---------------- fc1 ----------------
__global__ void __launch_bounds__(128) k_fc1(const float* fcb) {
    __shared__ u8 q[256];
    __shared__ float sred[32];
    int b = blockIdx.x, tid = threadIdx.x;
    float s2 = act_scale(2);
    for (int i = tid; i < 256; i += 128) q[i] = quant1(g_h2[(size_t)b * 256 + i], s2);
    __syncthreads();
    float acc = 0.0f;
    if (tid < 120) {
        #pragma unroll 8
        for (int k = 0; k < 256; k++) {
            int ai = (int)q[k] - 128;
            acc += __ldg(&g_M3[(size_t)(k * 128 + ai) * 120 + tid]);
        }
    }
    float s = s2 * g_sw[2];
    float val = 0.0f;
    if (tid < 120) {
        val = fmaxf(s * acc + __ldg(fcb + tid), 0.0f);
        g_h3[(size_t)b * 120 + tid] = val;
    }
    float bm = blockReduceMax(val, sred);
    if (tid == 0) atomicMax(&g_amax[3], __float_as_uint(bm));
}

// ---------------- fc2 ----------------
__global__ void __launch_bounds__(96) k_fc2(const float* fcb) {
    __shared__ u8 q[120];
    __shared__ float sred[32];
    int b = blockIdx.x, tid = threadIdx.x;
    float s3 = act_scale(3);
    for (int i = tid; i < 120; i += 96) q[i] = quant1(g_h3[(size_t)b * 120 + i], s3);
    __syncthreads();
    float acc = 0.0f;
    if (tid < 84) {
        #pragma unroll 8
        for (int k = 0; k < 120; k++) {
            int ai = (int)q[k] - 128;
            acc += __ldg(&g_M4[(size_t)(k * 128 + ai) * 84 + tid]);
        }
    }
    float s = s3 * g_sw[3];
    float val = 0.0f;
    if (tid < 84) {
        val = fmaxf(s * acc + __ldg(fcb + tid), 0.0f);
        g_h4[(size_t)b * 84 + tid] = val;
    }
    float bm = blockReduceMax(val, sred);
    if (tid == 0) atomicMax(&g_amax[4], __float_as_uint(bm));
}

// ---------------- fc3 ----------------
__global__ void __launch_bounds__(96) k_fc3(const float* fcb, float* out) {
    __shared__ u8 q[84];
    int b = blockIdx.x, tid = threadIdx.x;
    float s4 = act_scale(4);
    if (tid < 84) q[tid] = quant1(g_h4[(size_t)b * 84 + tid], s4);
    __syncthreads();
    if (tid < 10) {
        float acc = 0.0f;
        #pragma unroll 4
        for (int k = 0; k < 84; k++) {
            int ai = (int)q[k] - 128;
            acc += __ldg(&g_M5[(k * 128 + ai) * 10 + tid]);
        }
        out[b * 10 + tid] = s4 * g_sw[4] * acc + __ldg(fcb + tid);
    }
}

// ---------------- launch ----------------
extern "C" void kernel_launch(void* const* d_in, const int* in_sizes, int n_in,
                              void* d_out, int out_size) {
    const float* x   = (const float*)d_in[0];
    const float* lut = (const float*)d_in[1];
    const float* w1  = (const float*)d_in[2];
    const float* b1  = (const float*)d_in[3];
    const float* w2  = (const float*)d_in[4];
    const float* b2  = (const float*)d_in[5];
    const float* w3  = (const float*)d_in[6];
    const float* b3  = (const float*)d_in[7];
    const float* w4  = (const float*)d_in[8];
    const float* b4  = (const float*)d_in[9];
    const float* w5  = (const float*)d_in[10];
    const float* b5  = (const float*)d_in[11];
    float* out = (float*)d_out;

    float *M3p, *M4p, *M5p;
    u8 *qw3p, *qw4p, *qw5p;
    cudaGetSymbolAddress((void**)&M3p, g_M3);
    cudaGetSymbolAddress((void**)&M4p, g_M4);
    cudaGetSymbolAddress((void**)&M5p, g_M5);
    cudaGetSymbolAddress((void**)&qw3p, g_qw3);
    cudaGetSymbolAddress((void**)&qw4p, g_qw4);
    cudaGetSymbolAddress((void**)&qw5p, g_qw5);

    cudaFuncSetAttribute(k_conv1, cudaFuncAttributeMaxDynamicSharedMemorySize, C1_SMEM);

    // order: ncu's captured slot (#4) lands on k_conv1
    k_quant_w<<<5, 256>>>(w1, w2, w3, w4, w5);                      // 1
    k_maxabs<<<2048, 256>>>(x, BATCH * 784, 0);                     // 2
    k_buildM1<<<(25 * 256 * 8 + 255) / 256, 256>>>(lut);            // 3
    k_conv1<<<148, 576, C1_SMEM>>>(x, b1);                          // 4  <- profiled
    k_buildR2<<<(150 * 128 * 16 + 255) / 256, 256>>>(lut);          // 5
    k_conv2<<<BATCH / 8, 512>>>(b2);                                // 6
    k_buildM<<<(256 * 128 * 120 + 255) / 256, 256>>>(M3p, qw3p, lut, 256, 120, 120, 128, 128);
    k_buildM<<<(120 * 128 * 84 + 255) / 256, 256>>>(M4p, qw4p, lut, 120, 84, 84, 128, 128);
    k_buildM<<<(84 * 128 * 10 + 255) / 256, 256>>>(M5p, qw5p, lut, 84, 10, 10, 128, 128);
    k_fc1<<<BATCH, 128>>>(b3);
    k_fc2<<<BATCH, 96>>>(b4);
    k_fc3<<<BATCH, 96>>>(b5, out);
}